// round 8
// baseline (speedup 1.0000x reference)
#include <cuda_runtime.h>
#include <math.h>

#define NSTEP  98
#define NSAVE  49

// ---------------- constant table passed by value (constant memory) ----------
struct KTab {
    float4 a[NSAVE];   // {alpha+gamma, beta, gamma, 0}
    float4 v[NSAVE];   // {V0, V1, V2, V3}
};

// ---------------- host: build the universal table in fp64 ------------------
static void host_tsit2(double u0, double d0, const double cs[6], double* ru, double* rd)
{
    const double h = 0.01;
    const double a21 = 0.161;
    const double a31 = -0.008480655492356989, a32 = 0.335480655492357;
    const double a41 = 2.8971530571054935, a42 = -6.359448489975075, a43 = 4.3622954328695815;
    const double a51 = 5.325864828439257, a52 = -11.748883564062828, a53 = 7.4955393428898365, a54 = -0.09249506636175525;
    const double a61 = 5.86145544294642, a62 = -12.92096931784711, a63 = 8.159367898576159, a64 = -0.071584973281401, a65 = -0.028269050394068383;
    const double b1 = 0.09646076681806523, b2 = 0.01, b3 = 0.4798896504144996,
                 b4 = 1.379008574103742, b5 = -3.290069515436081, b6 = 2.324710524099774;

    double ku[6], kd[6], su, sd;
    su = u0; sd = d0;
    ku[0] = sd; kd[0] = -25.0*su - 10.0*sd + cs[0];
    su = u0 + h*(a21*ku[0]);                               sd = d0 + h*(a21*kd[0]);
    ku[1] = sd; kd[1] = -25.0*su - 10.0*sd + cs[1];
    su = u0 + h*(a31*ku[0]+a32*ku[1]);                     sd = d0 + h*(a31*kd[0]+a32*kd[1]);
    ku[2] = sd; kd[2] = -25.0*su - 10.0*sd + cs[2];
    su = u0 + h*(a41*ku[0]+a42*ku[1]+a43*ku[2]);           sd = d0 + h*(a41*kd[0]+a42*kd[1]+a43*kd[2]);
    ku[3] = sd; kd[3] = -25.0*su - 10.0*sd + cs[3];
    su = u0 + h*(a51*ku[0]+a52*ku[1]+a53*ku[2]+a54*ku[3]); sd = d0 + h*(a51*kd[0]+a52*kd[1]+a53*kd[2]+a54*kd[3]);
    ku[4] = sd; kd[4] = -25.0*su - 10.0*sd + cs[4];
    su = u0 + h*(a61*ku[0]+a62*ku[1]+a63*ku[2]+a64*ku[3]+a65*ku[4]);
    sd = d0 + h*(a61*kd[0]+a62*kd[1]+a63*kd[2]+a64*kd[3]+a65*kd[4]);
    ku[5] = sd; kd[5] = -25.0*su - 10.0*sd + cs[5];

    *ru = u0 + h*(b1*ku[0]+b2*ku[1]+b3*ku[2]+b4*ku[3]+b5*ku[4]+b6*ku[5]);
    *rd = d0 + h*(b1*kd[0]+b2*kd[1]+b3*kd[2]+b4*kd[3]+b5*kd[4]+b6*kd[5]);
}

static void build_ktab(KTab* kt)
{
    const double h = 0.01;
    const double a21 = 0.161;
    const double a31 = -0.008480655492356989, a32 = 0.335480655492357;
    const double a41 = 2.8971530571054935, a42 = -6.359448489975075, a43 = 4.3622954328695815;
    const double a51 = 5.325864828439257, a52 = -11.748883564062828, a53 = 7.4955393428898365, a54 = -0.09249506636175525;
    const double a61 = 5.86145544294642, a62 = -12.92096931784711, a63 = 8.159367898576159, a64 = -0.071584973281401, a65 = -0.028269050394068383;
    const double b1 = 0.09646076681806523, b2 = 0.01, b3 = 0.4798896504144996,
                 b4 = 1.379008574103742, b5 = -3.290069515436081, b6 = 2.324710524099774;

    // scalar phase ODE p' = -p: stage factors sig[s], step factor R
    double k1 = -1.0;
    double p2 = 1.0 + h*a21*k1;                               double k2 = -p2;
    double p3 = 1.0 + h*(a31*k1+a32*k2);                      double k3 = -p3;
    double p4 = 1.0 + h*(a41*k1+a42*k2+a43*k3);               double k4 = -p4;
    double p5 = 1.0 + h*(a51*k1+a52*k2+a53*k3+a54*k4);        double k5 = -p5;
    double p6 = 1.0 + h*(a61*k1+a62*k2+a63*k3+a64*k4+a65*k5); double k6 = -p6;
    double sig[6] = {1.0, p2, p3, p4, p5, p6};
    double R = 1.0 + h*(b1*k1+b2*k2+b3*k3+b4*k4+b5*k5+b6*k6);

    double C[4], H[4];
    for (int k = 0; k < 4; k++) { C[k] = exp(-(double)k / 3.0); H[k] = 4.0 / C[k]; }

    // one-step matrices via superposition
    double M[2][2], E[2], D[6][2];
    double z[6] = {0,0,0,0,0,0};
    host_tsit2(1.0, 0.0, z, &M[0][0], &M[1][0]);
    host_tsit2(0.0, 1.0, z, &M[0][1], &M[1][1]);
    double cg[6] = {25.0,25.0,25.0,25.0,25.0,25.0};
    host_tsit2(0.0, 0.0, cg, &E[0], &E[1]);
    for (int s = 0; s < 6; s++) {
        double ci[6] = {0,0,0,0,0,0};
        ci[s] = 1.0;
        host_tsit2(0.0, 0.0, ci, &D[s][0], &D[s][1]);
    }

    // per-step forcing response
    static double Dlin[NSTEP][2][4];
    double pn = 1.0;
    for (int n = 0; n < NSTEP; n++) {
        double A0[4] = {0,0,0,0}, A1[4] = {0,0,0,0};
        for (int s = 0; s < 6; s++) {
            double ps = sig[s] * pn;
            double psi[4], sw = 0.0;
            for (int k = 0; k < 4; k++) {
                double d = ps - C[k];
                psi[k] = exp(-H[k] * d * d);
                sw += psi[k];
            }
            double sc = ps / sw;
            for (int k = 0; k < 4; k++) {
                double w = psi[k] * sc;
                A0[k] += D[s][0] * w;
                A1[k] += D[s][1] * w;
            }
        }
        for (int k = 0; k < 4; k++) { Dlin[n][0][k] = A0[k]; Dlin[n][1][k] = A1[k]; }
        pn *= R;
    }

    // compose n = 2(t+1) steps per saved sample
    for (int t = 0; t < NSAVE; t++) {
        int n = 2 * (t + 1);
        double r0 = 1.0, r1 = 0.0;     // row vector e_u M^i
        double V[4] = {0,0,0,0};
        double S = 0.0;
        for (int i = 0; i < n; i++) {
            int j = n - 1 - i;
            for (int k = 0; k < 4; k++)
                V[k] += r0 * Dlin[j][0][k] + r1 * Dlin[j][1][k];
            S += r0 * E[0] + r1 * E[1];
            double nr0 = r0 * M[0][0] + r1 * M[1][0];
            double nr1 = r0 * M[0][1] + r1 * M[1][1];
            r0 = nr0; r1 = nr1;
        }
        // fold: u_t = (alpha+gamma)*u0 + beta*ud0 + (gamma + m)*gmu0
        kt->a[t] = make_float4((float)(r0 + S), (float)r1, (float)S, 0.0f);
        kt->v[t] = make_float4((float)V[0], (float)V[1], (float)V[2], (float)V[3]);
    }
}

// ---------------- device: batch-per-warp evaluation kernel ------------------
// Warp w owns batch b = w. Lane l: q = l&3 (action quad), rg = l>>2 (row group).
// Iteration k writes rows rg + 8k; warp store = contiguous 512B. Inputs for
// each (b,q) are loaded by 8 lanes at identical addresses (coalesced dedup).
__global__ void __launch_bounds__(256) ndp_main(
    const KTab kt,
    const float* __restrict__ iu,   // [B, 32] u|ud
    const float* __restrict__ rw,   // [B, 16, 4]
    const float* __restrict__ go,   // [B, 16]
    float* __restrict__ out,        // [B, 50, 16]
    int nwarp)                      // B
{
    __shared__ float4 sA[NSAVE];
    __shared__ float4 sV[NSAVE];
    {
        int t = threadIdx.x;
        if (t < NSAVE)                 sA[t] = kt.a[t];
        else if (t >= 64 && t < 64 + NSAVE) sV[t - 64] = kt.v[t - 64];
    }
    __syncthreads();

    int b = blockIdx.x * 8 + (threadIdx.x >> 5);   // warp index = batch
    if (b >= nwarp) return;
    int l  = threadIdx.x & 31;
    int q  = l & 3;
    int rg = l >> 2;

    const float4 u0  = *(const float4*)(iu + b * 32 + q * 4);
    const float4 ud0 = *(const float4*)(iu + b * 32 + 16 + q * 4);
    const float4 g   = *(const float4*)(go + b * 16 + q * 4);
    const float4 W0  = *(const float4*)(rw + b * 64 + q * 16);
    const float4 W1  = *(const float4*)(rw + b * 64 + q * 16 + 4);
    const float4 W2  = *(const float4*)(rw + b * 64 + q * 16 + 8);
    const float4 W3  = *(const float4*)(rw + b * 64 + q * 16 + 12);

    const float gm0 = g.x - u0.x, gm1 = g.y - u0.y, gm2 = g.z - u0.z, gm3 = g.w - u0.w;

    float* ob = out + (size_t)b * 800 + q * 4;

    #pragma unroll
    for (int k = 0; k < 7; k++) {
        int row = rg + 8 * k;
        if (row < 50) {
            float4 rr;
            if (row == 0) {
                rr = u0;
            } else {
                const int tt = row - 1;
                const float4 A = sA[tt];   // {alpha+gamma, beta, gamma, 0}
                const float4 V = sV[tt];
                float m;
                m    = V.x*W0.x + V.y*W0.y + V.z*W0.z + V.w*W0.w;
                rr.x = A.x*u0.x + A.y*ud0.x + (A.z + m)*gm0;
                m    = V.x*W1.x + V.y*W1.y + V.z*W1.z + V.w*W1.w;
                rr.y = A.x*u0.y + A.y*ud0.y + (A.z + m)*gm1;
                m    = V.x*W2.x + V.y*W2.y + V.z*W2.z + V.w*W2.w;
                rr.z = A.x*u0.z + A.y*ud0.z + (A.z + m)*gm2;
                m    = V.x*W3.x + V.y*W3.y + V.z*W3.z + V.w*W3.w;
                rr.w = A.x*u0.w + A.y*ud0.w + (A.z + m)*gm3;
            }
            *(float4*)(ob + row * 16) = rr;
        }
    }
}

extern "C" void kernel_launch(void* const* d_in, const int* in_sizes, int n_in,
                              void* d_out, int out_size)
{
    const float* iu = (const float*)d_in[0];   // init_u_udot [B, 32]
    const float* rw = (const float*)d_in[1];   // rbf_weights [B, 64]
    const float* go = (const float*)d_in[2];   // goals [B, 16]
    float* out = (float*)d_out;

    int B  = in_sizes[0] / 32;                  // warps (one per batch)
    int nb = (B + 7) / 8;                       // 8 warps per 256-thread block

    KTab kt;                 // computed on host at capture time only
    build_ktab(&kt);

    ndp_main<<<nb, 256>>>(kt, iu, rw, go, out, B);
}

// round 10
// speedup vs baseline: 1.0445x; 1.0445x over previous
#include <cuda_runtime.h>
#include <math.h>

#define NSTEP  98
#define NSAVE  49
#define NROW   50   // table rows incl. identity row 0

// ---------------- constant table passed by value (constant memory) ----------
struct KTab {
    float4 a[NROW];   // {alpha+gamma, beta, gamma, 0};  a[0] = {1,0,0,0}
    float4 v[NROW];   // {V0, V1, V2, V3};               v[0] = 0
};

// ---------------- host: build the universal table in fp64 ------------------
static void host_tsit2(double u0, double d0, const double cs[6], double* ru, double* rd)
{
    const double h = 0.01;
    const double a21 = 0.161;
    const double a31 = -0.008480655492356989, a32 = 0.335480655492357;
    const double a41 = 2.8971530571054935, a42 = -6.359448489975075, a43 = 4.3622954328695815;
    const double a51 = 5.325864828439257, a52 = -11.748883564062828, a53 = 7.4955393428898365, a54 = -0.09249506636175525;
    const double a61 = 5.86145544294642, a62 = -12.92096931784711, a63 = 8.159367898576159, a64 = -0.071584973281401, a65 = -0.028269050394068383;
    const double b1 = 0.09646076681806523, b2 = 0.01, b3 = 0.4798896504144996,
                 b4 = 1.379008574103742, b5 = -3.290069515436081, b6 = 2.324710524099774;

    double ku[6], kd[6], su, sd;
    su = u0; sd = d0;
    ku[0] = sd; kd[0] = -25.0*su - 10.0*sd + cs[0];
    su = u0 + h*(a21*ku[0]);                               sd = d0 + h*(a21*kd[0]);
    ku[1] = sd; kd[1] = -25.0*su - 10.0*sd + cs[1];
    su = u0 + h*(a31*ku[0]+a32*ku[1]);                     sd = d0 + h*(a31*kd[0]+a32*kd[1]);
    ku[2] = sd; kd[2] = -25.0*su - 10.0*sd + cs[2];
    su = u0 + h*(a41*ku[0]+a42*ku[1]+a43*ku[2]);           sd = d0 + h*(a41*kd[0]+a42*kd[1]+a43*kd[2]);
    ku[3] = sd; kd[3] = -25.0*su - 10.0*sd + cs[3];
    su = u0 + h*(a51*ku[0]+a52*ku[1]+a53*ku[2]+a54*ku[3]); sd = d0 + h*(a51*kd[0]+a52*kd[1]+a53*kd[2]+a54*kd[3]);
    ku[4] = sd; kd[4] = -25.0*su - 10.0*sd + cs[4];
    su = u0 + h*(a61*ku[0]+a62*ku[1]+a63*ku[2]+a64*ku[3]+a65*ku[4]);
    sd = d0 + h*(a61*kd[0]+a62*kd[1]+a63*kd[2]+a64*kd[3]+a65*kd[4]);
    ku[5] = sd; kd[5] = -25.0*su - 10.0*sd + cs[5];

    *ru = u0 + h*(b1*ku[0]+b2*ku[1]+b3*ku[2]+b4*ku[3]+b5*ku[4]+b6*ku[5]);
    *rd = d0 + h*(b1*kd[0]+b2*kd[1]+b3*kd[2]+b4*kd[3]+b5*kd[4]+b6*kd[5]);
}

static void build_ktab(KTab* kt)
{
    const double h = 0.01;
    const double a21 = 0.161;
    const double a31 = -0.008480655492356989, a32 = 0.335480655492357;
    const double a41 = 2.8971530571054935, a42 = -6.359448489975075, a43 = 4.3622954328695815;
    const double a51 = 5.325864828439257, a52 = -11.748883564062828, a53 = 7.4955393428898365, a54 = -0.09249506636175525;
    const double a61 = 5.86145544294642, a62 = -12.92096931784711, a63 = 8.159367898576159, a64 = -0.071584973281401, a65 = -0.028269050394068383;
    const double b1 = 0.09646076681806523, b2 = 0.01, b3 = 0.4798896504144996,
                 b4 = 1.379008574103742, b5 = -3.290069515436081, b6 = 2.324710524099774;

    // scalar phase ODE p' = -p: stage factors sig[s], step factor R
    double k1 = -1.0;
    double p2 = 1.0 + h*a21*k1;                               double k2 = -p2;
    double p3 = 1.0 + h*(a31*k1+a32*k2);                      double k3 = -p3;
    double p4 = 1.0 + h*(a41*k1+a42*k2+a43*k3);               double k4 = -p4;
    double p5 = 1.0 + h*(a51*k1+a52*k2+a53*k3+a54*k4);        double k5 = -p5;
    double p6 = 1.0 + h*(a61*k1+a62*k2+a63*k3+a64*k4+a65*k5); double k6 = -p6;
    double sig[6] = {1.0, p2, p3, p4, p5, p6};
    double R = 1.0 + h*(b1*k1+b2*k2+b3*k3+b4*k4+b5*k5+b6*k6);

    double C[4], H[4];
    for (int k = 0; k < 4; k++) { C[k] = exp(-(double)k / 3.0); H[k] = 4.0 / C[k]; }

    // one-step matrices via superposition
    double M[2][2], E[2], D[6][2];
    double z[6] = {0,0,0,0,0,0};
    host_tsit2(1.0, 0.0, z, &M[0][0], &M[1][0]);
    host_tsit2(0.0, 1.0, z, &M[0][1], &M[1][1]);
    double cg[6] = {25.0,25.0,25.0,25.0,25.0,25.0};
    host_tsit2(0.0, 0.0, cg, &E[0], &E[1]);
    for (int s = 0; s < 6; s++) {
        double ci[6] = {0,0,0,0,0,0};
        ci[s] = 1.0;
        host_tsit2(0.0, 0.0, ci, &D[s][0], &D[s][1]);
    }

    // per-step forcing response
    static double Dlin[NSTEP][2][4];
    double pn = 1.0;
    for (int n = 0; n < NSTEP; n++) {
        double A0[4] = {0,0,0,0}, A1[4] = {0,0,0,0};
        for (int s = 0; s < 6; s++) {
            double ps = sig[s] * pn;
            double psi[4], sw = 0.0;
            for (int k = 0; k < 4; k++) {
                double d = ps - C[k];
                psi[k] = exp(-H[k] * d * d);
                sw += psi[k];
            }
            double sc = ps / sw;
            for (int k = 0; k < 4; k++) {
                double w = psi[k] * sc;
                A0[k] += D[s][0] * w;
                A1[k] += D[s][1] * w;
            }
        }
        for (int k = 0; k < 4; k++) { Dlin[n][0][k] = A0[k]; Dlin[n][1][k] = A1[k]; }
        pn *= R;
    }

    // row 0: identity (u_0 = u0)
    kt->a[0] = make_float4(1.0f, 0.0f, 0.0f, 0.0f);
    kt->v[0] = make_float4(0.0f, 0.0f, 0.0f, 0.0f);

    // rows 1..49: compose n = 2*row steps
    for (int t = 0; t < NSAVE; t++) {
        int n = 2 * (t + 1);
        double r0 = 1.0, r1 = 0.0;     // row vector e_u M^i
        double V[4] = {0,0,0,0};
        double S = 0.0;
        for (int i = 0; i < n; i++) {
            int j = n - 1 - i;
            for (int k = 0; k < 4; k++)
                V[k] += r0 * Dlin[j][0][k] + r1 * Dlin[j][1][k];
            S += r0 * E[0] + r1 * E[1];
            double nr0 = r0 * M[0][0] + r1 * M[1][0];
            double nr1 = r0 * M[0][1] + r1 * M[1][1];
            r0 = nr0; r1 = nr1;
        }
        // u_t = (alpha+gamma)*u0 + beta*ud0 + gamma*gm + (V . (gm*W))
        kt->a[t + 1] = make_float4((float)(r0 + S), (float)r1, (float)S, 0.0f);
        kt->v[t + 1] = make_float4((float)V[0], (float)V[1], (float)V[2], (float)V[3]);
    }
}

// ---------------- device: warp-per-batch, dense-store kernel ----------------
// Warp = one batch. Lane l: q = l&3 (action quad), rg = l>>2 (row group 0..7).
// Iteration k (k=0..5) writes row rg+8k -> warp store = 512B contiguous.
// Rows 48,49 are written by lanes 0..7 in one extra predicated store.
// Inputs per (b,q) read by 8 lanes at identical addresses (coalescer dedup).
__global__ void __launch_bounds__(256) ndp_main(
    const KTab kt,
    const float* __restrict__ iu,   // [B, 32] u|ud
    const float* __restrict__ rw,   // [B, 16, 4]
    const float* __restrict__ go,   // [B, 16]
    float* __restrict__ out,        // [B, 50, 16]
    int nwarp)                      // B
{
    __shared__ float4 sA[NROW];
    __shared__ float4 sV[NROW];
    {
        int t = threadIdx.x;
        if (t < NROW)                        sA[t] = kt.a[t];
        else if (t >= 64 && t < 64 + NROW)   sV[t - 64] = kt.v[t - 64];
    }
    __syncthreads();

    int b = blockIdx.x * 8 + (threadIdx.x >> 5);   // warp index = batch
    if (b >= nwarp) return;
    int l  = threadIdx.x & 31;
    int q  = l & 3;
    int rg = l >> 2;

    const float4 u0  = *(const float4*)(iu + b * 32 + q * 4);
    const float4 ud0 = *(const float4*)(iu + b * 32 + 16 + q * 4);
    const float4 g   = *(const float4*)(go + b * 16 + q * 4);
    const float4 W0  = *(const float4*)(rw + b * 64 + q * 16);
    const float4 W1  = *(const float4*)(rw + b * 64 + q * 16 + 4);
    const float4 W2  = *(const float4*)(rw + b * 64 + q * 16 + 8);
    const float4 W3  = *(const float4*)(rw + b * 64 + q * 16 + 12);

    const float gm0 = g.x - u0.x, gm1 = g.y - u0.y, gm2 = g.z - u0.z, gm3 = g.w - u0.w;

    // fold gm into the weights once: per component c, m_c = V . (gm_c * W_c)
    const float4 X0 = make_float4(W0.x*gm0, W0.y*gm0, W0.z*gm0, W0.w*gm0);
    const float4 X1 = make_float4(W1.x*gm1, W1.y*gm1, W1.z*gm1, W1.w*gm1);
    const float4 X2 = make_float4(W2.x*gm2, W2.y*gm2, W2.z*gm2, W2.w*gm2);
    const float4 X3 = make_float4(W3.x*gm3, W3.y*gm3, W3.z*gm3, W3.w*gm3);

    float* ob = out + (size_t)b * 800 + q * 4;

#define ROW_EVAL(row, rr)                                                    \
    {                                                                        \
        const float4 A = sA[row];  /* {alpha+gamma, beta, gamma, 0} */       \
        const float4 V = sV[row];                                            \
        rr.x = A.x*u0.x + A.y*ud0.x + A.z*gm0                                \
             + V.x*X0.x + V.y*X0.y + V.z*X0.z + V.w*X0.w;                    \
        rr.y = A.x*u0.y + A.y*ud0.y + A.z*gm1                                \
             + V.x*X1.x + V.y*X1.y + V.z*X1.z + V.w*X1.w;                    \
        rr.z = A.x*u0.z + A.y*ud0.z + A.z*gm2                                \
             + V.x*X2.x + V.y*X2.y + V.z*X2.z + V.w*X2.w;                    \
        rr.w = A.x*u0.w + A.y*ud0.w + A.z*gm3                                \
             + V.x*X3.x + V.y*X3.y + V.z*X3.z + V.w*X3.w;                    \
    }

    #pragma unroll
    for (int k = 0; k < 6; k++) {
        int row = rg + 8 * k;               // rows 0..47, no bounds check
        float4 rr;
        ROW_EVAL(row, rr);
        *(float4*)(ob + row * 16) = rr;
    }

    // rows 48, 49: lanes 0..7 (rg 0..1), one predicated 128B store
    if (l < 8) {
        int row = 48 + rg;
        float4 rr;
        ROW_EVAL(row, rr);
        *(float4*)(ob + row * 16) = rr;
    }
#undef ROW_EVAL
}

extern "C" void kernel_launch(void* const* d_in, const int* in_sizes, int n_in,
                              void* d_out, int out_size)
{
    const float* iu = (const float*)d_in[0];   // init_u_udot [B, 32]
    const float* rw = (const float*)d_in[1];   // rbf_weights [B, 64]
    const float* go = (const float*)d_in[2];   // goals [B, 16]
    float* out = (float*)d_out;

    int B  = in_sizes[0] / 32;                  // one warp per batch
    int nb = (B + 7) / 8;                       // 8 warps per 256-thread block

    KTab kt;                 // computed on host at capture time only
    build_ktab(&kt);

    ndp_main<<<nb, 256>>>(kt, iu, rw, go, out, B);
}

// round 11
// speedup vs baseline: 1.1315x; 1.0833x over previous
#include <cuda_runtime.h>
#include <math.h>

#define NSTEP  98
#define NSAVE  49

// ---------------- constant table passed by value (constant memory) ----------
struct KTab {
    float4 a[NSAVE];   // {alpha+gamma, beta, gamma, 0}
    float4 v[NSAVE];   // {V0, V1, V2, V3}
};

// ---------------- host: build the universal table in fp64 ------------------
static void host_tsit2(double u0, double d0, const double cs[6], double* ru, double* rd)
{
    const double h = 0.01;
    const double a21 = 0.161;
    const double a31 = -0.008480655492356989, a32 = 0.335480655492357;
    const double a41 = 2.8971530571054935, a42 = -6.359448489975075, a43 = 4.3622954328695815;
    const double a51 = 5.325864828439257, a52 = -11.748883564062828, a53 = 7.4955393428898365, a54 = -0.09249506636175525;
    const double a61 = 5.86145544294642, a62 = -12.92096931784711, a63 = 8.159367898576159, a64 = -0.071584973281401, a65 = -0.028269050394068383;
    const double b1 = 0.09646076681806523, b2 = 0.01, b3 = 0.4798896504144996,
                 b4 = 1.379008574103742, b5 = -3.290069515436081, b6 = 2.324710524099774;

    double ku[6], kd[6], su, sd;
    su = u0; sd = d0;
    ku[0] = sd; kd[0] = -25.0*su - 10.0*sd + cs[0];
    su = u0 + h*(a21*ku[0]);                               sd = d0 + h*(a21*kd[0]);
    ku[1] = sd; kd[1] = -25.0*su - 10.0*sd + cs[1];
    su = u0 + h*(a31*ku[0]+a32*ku[1]);                     sd = d0 + h*(a31*kd[0]+a32*kd[1]);
    ku[2] = sd; kd[2] = -25.0*su - 10.0*sd + cs[2];
    su = u0 + h*(a41*ku[0]+a42*ku[1]+a43*ku[2]);           sd = d0 + h*(a41*kd[0]+a42*kd[1]+a43*kd[2]);
    ku[3] = sd; kd[3] = -25.0*su - 10.0*sd + cs[3];
    su = u0 + h*(a51*ku[0]+a52*ku[1]+a53*ku[2]+a54*ku[3]); sd = d0 + h*(a51*kd[0]+a52*kd[1]+a53*kd[2]+a54*kd[3]);
    ku[4] = sd; kd[4] = -25.0*su - 10.0*sd + cs[4];
    su = u0 + h*(a61*ku[0]+a62*ku[1]+a63*ku[2]+a64*ku[3]+a65*ku[4]);
    sd = d0 + h*(a61*kd[0]+a62*kd[1]+a63*kd[2]+a64*kd[3]+a65*kd[4]);
    ku[5] = sd; kd[5] = -25.0*su - 10.0*sd + cs[5];

    *ru = u0 + h*(b1*ku[0]+b2*ku[1]+b3*ku[2]+b4*ku[3]+b5*ku[4]+b6*ku[5]);
    *rd = d0 + h*(b1*kd[0]+b2*kd[1]+b3*kd[2]+b4*kd[3]+b5*kd[4]+b6*kd[5]);
}

static void build_ktab(KTab* kt)
{
    const double h = 0.01;
    const double a21 = 0.161;
    const double a31 = -0.008480655492356989, a32 = 0.335480655492357;
    const double a41 = 2.8971530571054935, a42 = -6.359448489975075, a43 = 4.3622954328695815;
    const double a51 = 5.325864828439257, a52 = -11.748883564062828, a53 = 7.4955393428898365, a54 = -0.09249506636175525;
    const double a61 = 5.86145544294642, a62 = -12.92096931784711, a63 = 8.159367898576159, a64 = -0.071584973281401, a65 = -0.028269050394068383;
    const double b1 = 0.09646076681806523, b2 = 0.01, b3 = 0.4798896504144996,
                 b4 = 1.379008574103742, b5 = -3.290069515436081, b6 = 2.324710524099774;

    // scalar phase ODE p' = -p: stage factors sig[s], step factor R
    double k1 = -1.0;
    double p2 = 1.0 + h*a21*k1;                               double k2 = -p2;
    double p3 = 1.0 + h*(a31*k1+a32*k2);                      double k3 = -p3;
    double p4 = 1.0 + h*(a41*k1+a42*k2+a43*k3);               double k4 = -p4;
    double p5 = 1.0 + h*(a51*k1+a52*k2+a53*k3+a54*k4);        double k5 = -p5;
    double p6 = 1.0 + h*(a61*k1+a62*k2+a63*k3+a64*k4+a65*k5); double k6 = -p6;
    double sig[6] = {1.0, p2, p3, p4, p5, p6};
    double R = 1.0 + h*(b1*k1+b2*k2+b3*k3+b4*k4+b5*k5+b6*k6);

    double C[4], H[4];
    for (int k = 0; k < 4; k++) { C[k] = exp(-(double)k / 3.0); H[k] = 4.0 / C[k]; }

    // one-step matrices via superposition
    double M[2][2], E[2], D[6][2];
    double z[6] = {0,0,0,0,0,0};
    host_tsit2(1.0, 0.0, z, &M[0][0], &M[1][0]);
    host_tsit2(0.0, 1.0, z, &M[0][1], &M[1][1]);
    double cg[6] = {25.0,25.0,25.0,25.0,25.0,25.0};
    host_tsit2(0.0, 0.0, cg, &E[0], &E[1]);
    for (int s = 0; s < 6; s++) {
        double ci[6] = {0,0,0,0,0,0};
        ci[s] = 1.0;
        host_tsit2(0.0, 0.0, ci, &D[s][0], &D[s][1]);
    }

    // per-step forcing response
    static double Dlin[NSTEP][2][4];
    double pn = 1.0;
    for (int n = 0; n < NSTEP; n++) {
        double A0[4] = {0,0,0,0}, A1[4] = {0,0,0,0};
        for (int s = 0; s < 6; s++) {
            double ps = sig[s] * pn;
            double psi[4], sw = 0.0;
            for (int k = 0; k < 4; k++) {
                double d = ps - C[k];
                psi[k] = exp(-H[k] * d * d);
                sw += psi[k];
            }
            double sc = ps / sw;
            for (int k = 0; k < 4; k++) {
                double w = psi[k] * sc;
                A0[k] += D[s][0] * w;
                A1[k] += D[s][1] * w;
            }
        }
        for (int k = 0; k < 4; k++) { Dlin[n][0][k] = A0[k]; Dlin[n][1][k] = A1[k]; }
        pn *= R;
    }

    // compose n = 2(t+1) steps per saved sample
    for (int t = 0; t < NSAVE; t++) {
        int n = 2 * (t + 1);
        double r0 = 1.0, r1 = 0.0;     // row vector e_u M^i
        double V[4] = {0,0,0,0};
        double S = 0.0;
        for (int i = 0; i < n; i++) {
            int j = n - 1 - i;
            for (int k = 0; k < 4; k++)
                V[k] += r0 * Dlin[j][0][k] + r1 * Dlin[j][1][k];
            S += r0 * E[0] + r1 * E[1];
            double nr0 = r0 * M[0][0] + r1 * M[1][0];
            double nr1 = r0 * M[0][1] + r1 * M[1][1];
            r0 = nr0; r1 = nr1;
        }
        // fold: u_t = (alpha+gamma)*u0 + beta*ud0 + (gamma + m)*gmu0
        kt->a[t] = make_float4((float)(r0 + S), (float)r1, (float)S, 0.0f);
        kt->v[t] = make_float4((float)V[0], (float)V[1], (float)V[2], (float)V[3]);
    }
}

// ---------------- device: single memory-bound evaluation kernel -------------
// Grid split in two halves of nb blocks each: blocks [0, nb) write rows 0..25
// (tc=0), blocks [nb, 2nb) write rows 26..49 (tc=1). tc is block-uniform.
// All output stores are streaming (st.global.cs): evict-first, keeps inputs
// L2-resident across graph replays and eagerly drains output lines to DRAM.
__global__ void __launch_bounds__(256, 6) ndp_main(
    const KTab kt,
    const float* __restrict__ iu,   // [B, 32] u|ud
    const float* __restrict__ rw,   // [B, 16, 4]
    const float* __restrict__ go,   // [B, 16]
    float* __restrict__ out,        // [B, 50, 16]
    int nb,                         // blocks per half
    int nq)                         // B*4 threads per half
{
    int bb = blockIdx.x;
    int tc = (bb >= nb) ? 1 : 0;
    int r  = (bb - tc * nb) * blockDim.x + threadIdx.x;
    if (r >= nq) return;
    int b = r >> 2;
    int q = r & 3;

    const float4 u0  = *(const float4*)(iu + b * 32 + q * 4);
    const float4 ud0 = *(const float4*)(iu + b * 32 + 16 + q * 4);
    const float4 g   = *(const float4*)(go + b * 16 + q * 4);
    const float4 W0  = *(const float4*)(rw + b * 64 + q * 16);
    const float4 W1  = *(const float4*)(rw + b * 64 + q * 16 + 4);
    const float4 W2  = *(const float4*)(rw + b * 64 + q * 16 + 8);
    const float4 W3  = *(const float4*)(rw + b * 64 + q * 16 + 12);

    const float gm0 = g.x - u0.x, gm1 = g.y - u0.y, gm2 = g.z - u0.z, gm3 = g.w - u0.w;

    float* ob = out + (size_t)b * 800 + q * 4;

#define ROW(tt)                                                              \
    {                                                                        \
        const float4 A = kt.a[tt];  /* {alpha+gamma, beta, gamma, 0} */      \
        const float4 V = kt.v[tt];                                           \
        float4 rr; float m;                                                  \
        m    = V.x*W0.x + V.y*W0.y + V.z*W0.z + V.w*W0.w;                    \
        rr.x = A.x*u0.x + A.y*ud0.x + (A.z + m)*gm0;                         \
        m    = V.x*W1.x + V.y*W1.y + V.z*W1.z + V.w*W1.w;                    \
        rr.y = A.x*u0.y + A.y*ud0.y + (A.z + m)*gm1;                         \
        m    = V.x*W2.x + V.y*W2.y + V.z*W2.z + V.w*W2.w;                    \
        rr.z = A.x*u0.z + A.y*ud0.z + (A.z + m)*gm2;                         \
        m    = V.x*W3.x + V.y*W3.y + V.z*W3.z + V.w*W3.w;                    \
        rr.w = A.x*u0.w + A.y*ud0.w + (A.z + m)*gm3;                         \
        __stcs((float4*)(ob + ((tt) + 1) * 16), rr);                         \
    }

    if (tc == 0) {
        __stcs((float4*)ob, u0);           // row 0 = t=0 sample
        #pragma unroll
        for (int tt = 0; tt < 25; tt++) ROW(tt);
    } else {
        #pragma unroll
        for (int tt = 25; tt < NSAVE; tt++) ROW(tt);
    }
#undef ROW
}

extern "C" void kernel_launch(void* const* d_in, const int* in_sizes, int n_in,
                              void* d_out, int out_size)
{
    const float* iu = (const float*)d_in[0];   // init_u_udot [B, 32]
    const float* rw = (const float*)d_in[1];   // rbf_weights [B, 64]
    const float* go = (const float*)d_in[2];   // goals [B, 16]
    float* out = (float*)d_out;

    int B  = in_sizes[0] / 32;
    int nq = B * 4;                     // threads per half
    int nb = (nq + 255) / 256;          // blocks per half

    KTab kt;                 // computed on host at capture time only
    build_ktab(&kt);

    ndp_main<<<nb * 2, 256>>>(kt, iu, rw, go, out, nb, nq);
}